// round 6
// baseline (speedup 1.0000x reference)
#include <cuda_runtime.h>
#include <math.h>

#define N_NODES 50000
#define N_EDGES 400000
#define F_DIM   128
#define N_TYPES 100
#define N_RBF   20
#define CUTOFF  5.0f
#define F3      (3 * F_DIM)   // 384

#define SCAN_B  256
#define SCAN_NB ((N_NODES + SCAN_B - 1) / SCAN_B)   // 196
#define ZERO_NB ((N_NODES + 127) / 128)             // 391

// -------- device scratch (no allocations allowed) --------
__device__ int   g_count[N_NODES];
__device__ int   g_start[N_NODES + 1];
__device__ int   g_cursor[N_NODES];
__device__ int   g_sorted[N_EDGES];
__device__ int   g_partial[SCAN_NB];
__device__ float g_phi[N_TYPES * F3];   // 100 x 384

// per-edge packed row: [0..19]=rbf, [20..22]=rel*dist, [23]=pad,
// [24]=src(int bits), [25]=typ(int bits), [26..31]=pad   => 128 bytes
struct __align__(16) EdgeRow { float v[32]; };
__device__ EdgeRow g_edat[N_EDGES];     // 51.2 MB

// ---------------------------------------------------------
// Fused init: blocks [0, ZERO_NB) zero the histogram;
// blocks [ZERO_NB, ZERO_NB+N_TYPES) compute phi for one atom type each.
__global__ void init_kernel(const float* __restrict__ emb_table,
                            const float* __restrict__ w1, const float* __restrict__ b1,
                            const float* __restrict__ w2, const float* __restrict__ b2) {
    if (blockIdx.x < ZERO_NB) {
        int i = blockIdx.x * 128 + threadIdx.x;
        if (i < N_NODES) g_count[i] = 0;
        return;
    }
    int t = blockIdx.x - ZERO_NB;   // atom type
    int f = threadIdx.x;            // 0..127
    __shared__ float es[F_DIM];
    __shared__ float hs[F_DIM];
    es[f] = emb_table[t * F_DIM + f];
    __syncthreads();
    float h = b1[f];
#pragma unroll 8
    for (int k = 0; k < F_DIM; k++)
        h = fmaf(es[k], w1[k * F_DIM + f], h);
    h = h / (1.0f + expf(-h));   // silu
    hs[f] = h;
    __syncthreads();
    float o0 = b2[f], o1 = b2[F_DIM + f], o2 = b2[2 * F_DIM + f];
#pragma unroll 8
    for (int k = 0; k < F_DIM; k++) {
        float hk = hs[k];
        const float* w2r = w2 + k * F3;
        o0 = fmaf(hk, w2r[f],             o0);
        o1 = fmaf(hk, w2r[F_DIM + f],     o1);
        o2 = fmaf(hk, w2r[2 * F_DIM + f], o2);
    }
    g_phi[t * F3 + f]             = o0;
    g_phi[t * F3 + F_DIM + f]     = o1;
    g_phi[t * F3 + 2 * F_DIM + f] = o2;
}

// ---------------------------------------------------------
__global__ void hist_kernel(const int* __restrict__ edge_dst) {
    int e = blockIdx.x * blockDim.x + threadIdx.x;
    if (e < N_EDGES) atomicAdd(&g_count[edge_dst[e]], 1);
}

// ---------------------------------------------------------
__global__ void scan1_kernel() {
    __shared__ int wsum[SCAN_B / 32];
    int t = threadIdx.x;
    int i = blockIdx.x * SCAN_B + t;
    int v = (i < N_NODES) ? g_count[i] : 0;
    for (int off = 16; off > 0; off >>= 1)
        v += __shfl_down_sync(0xffffffffu, v, off);
    if ((t & 31) == 0) wsum[t >> 5] = v;
    __syncthreads();
    if (t < SCAN_B / 32) {
        int s = wsum[t];
        for (int off = SCAN_B / 64; off > 0; off >>= 1)
            s += __shfl_down_sync(0xffu, s, off);
        if (t == 0) g_partial[blockIdx.x] = s;
    }
}

// ---------------------------------------------------------
// Scan stage 2+3 fused (each block re-reduces the partials for its offset)
__global__ void scan23_kernel() {
    __shared__ int wsum[SCAN_B / 32];
    __shared__ int s_boff, s_total;
    int t = threadIdx.x;
    {
        int p = (t < SCAN_NB) ? g_partial[t] : 0;
        int vm = (t < (int)blockIdx.x) ? p : 0;
        int va = p;
        for (int off = 16; off > 0; off >>= 1) {
            vm += __shfl_down_sync(0xffffffffu, vm, off);
            va += __shfl_down_sync(0xffffffffu, va, off);
        }
        __shared__ int wm[SCAN_B / 32], wa[SCAN_B / 32];
        if ((t & 31) == 0) { wm[t >> 5] = vm; wa[t >> 5] = va; }
        __syncthreads();
        if (t == 0) {
            int sm = 0, sa = 0;
#pragma unroll
            for (int w = 0; w < SCAN_B / 32; w++) { sm += wm[w]; sa += wa[w]; }
            s_boff = sm; s_total = sa;
        }
        __syncthreads();
    }
    if (blockIdx.x == 0 && t == 0) g_start[N_NODES] = s_total;

    int i = blockIdx.x * SCAN_B + t;
    int v = (i < N_NODES) ? g_count[i] : 0;
    int orig = v;
    for (int off = 1; off < 32; off <<= 1) {
        int u = __shfl_up_sync(0xffffffffu, v, off);
        if ((t & 31) >= off) v += u;
    }
    if ((t & 31) == 31) wsum[t >> 5] = v;
    __syncthreads();
    if (t < SCAN_B / 32) {
        int s = wsum[t];
        for (int off = 1; off < SCAN_B / 32; off <<= 1) {
            int u = __shfl_up_sync(0xffu, s, off);
            if (t >= off) s += u;
        }
        wsum[t] = s;
    }
    __syncthreads();
    int warp = t >> 5;
    int excl = v - orig + ((warp > 0) ? wsum[warp - 1] : 0) + s_boff;
    if (i < N_NODES) {
        g_start[i]  = excl;
        g_cursor[i] = excl;
    }
}

// ---------------------------------------------------------
__global__ void scatter_kernel(const int* __restrict__ edge_dst) {
    int e = blockIdx.x * blockDim.x + threadIdx.x;
    if (e < N_EDGES) {
        int p = atomicAdd(&g_cursor[edge_dst[e]], 1);
        g_sorted[p] = e;
    }
}

// ---------------------------------------------------------
// Geometry kernel: one thread per sorted-edge slot. Full edge parallelism.
__global__ void geom_kernel(const float* __restrict__ pos,
                            const int*   __restrict__ z,
                            const int*   __restrict__ edge_src,
                            const int*   __restrict__ edge_dst) {
    int i = blockIdx.x * blockDim.x + threadIdx.x;
    if (i >= N_EDGES) return;
    int e = g_sorted[i];
    int s = __ldg(&edge_src[e]);
    int d = __ldg(&edge_dst[e]);
    int ty = __ldg(&z[s]);
    float rx = __ldg(&pos[d * 3 + 0]) - __ldg(&pos[s * 3 + 0]);
    float ry = __ldg(&pos[d * 3 + 1]) - __ldg(&pos[s * 3 + 1]);
    float rz = __ldg(&pos[d * 3 + 2]) - __ldg(&pos[s * 3 + 2]);
    float dist = sqrtf(rx * rx + ry * ry + rz * rz);
    float inv  = 1.0f / dist;

    float row[32];
    float a = 3.14159265358979323846f * dist * (1.0f / CUTOFF);
    float s1, c1;
    sincosf(a, &s1, &c1);
    float twoc = 2.0f * c1;
    float sp = 0.0f, sc = s1;          // sin(0), sin(a)
#pragma unroll
    for (int k = 0; k < N_RBF; k++) {  // sin((k+1)a), stable Chebyshev recurrence
        row[k] = sc * inv;
        float nx = twoc * sc - sp;
        sp = sc; sc = nx;
    }
    row[20] = rx * dist;
    row[21] = ry * dist;
    row[22] = rz * dist;
    row[23] = 0.0f;
    row[24] = __int_as_float(s);
    row[25] = __int_as_float(ty);
    row[26] = row[27] = row[28] = row[29] = row[30] = row[31] = 0.0f;

    float4* dst4 = reinterpret_cast<float4*>(g_edat[i].v);
    const float4* src4 = reinterpret_cast<const float4*>(row);
#pragma unroll
    for (int j = 0; j < 8; j++) dst4[j] = src4[j];
}

// ---------------------------------------------------------
// Main: one block (128 threads) per destination node, thread f = channel f.
// No shared memory, no barriers: per-edge data comes as one 128B row
// (uniform LDG.128s -> single-line L1 broadcast).
__global__ __launch_bounds__(128, 4)
void main_kernel(const float* __restrict__ eq,
                 const float* __restrict__ emb_table,
                 const float* __restrict__ w_rbf,
                 const float* __restrict__ b_rbf,
                 const int*   __restrict__ z,
                 float* __restrict__ out_emb,
                 float* __restrict__ out_eq) {
    int f = threadIdx.x;
    int node = blockIdx.x;

    int e0 = g_start[node];
    int e1 = __ldg(&g_start[node + 1]);
    int zi = __ldg(&z[node]);

    // per-thread w_rbf columns in registers (60 regs)
    float wr0[N_RBF], wr1[N_RBF], wr2[N_RBF];
#pragma unroll
    for (int k = 0; k < N_RBF; k++) {
        const float* row = w_rbf + k * F3;
        wr0[k] = row[f];
        wr1[k] = row[F_DIM + f];
        wr2[k] = row[2 * F_DIM + f];
    }
    const float br0 = b_rbf[f], br1 = b_rbf[F_DIM + f], br2 = b_rbf[2 * F_DIM + f];

    float acc0 = 0.f, aq0 = 0.f, aq1 = 0.f, aq2 = 0.f;

#pragma unroll 2
    for (int i = e0; i < e1; i++) {
        const float4* row = reinterpret_cast<const float4*>(g_edat[i].v);
        float4 a0 = __ldg(row + 0);
        float4 a1 = __ldg(row + 1);
        float4 a2 = __ldg(row + 2);
        float4 a3 = __ldg(row + 3);
        float4 a4 = __ldg(row + 4);
        float4 rd = __ldg(row + 5);
        float4 mt = __ldg(row + 6);
        int s  = __float_as_int(mt.x);
        int ty = __float_as_int(mt.y);

        const float* ph = g_phi + ty * F3;
        float p0 = __ldg(&ph[f]);
        float p1 = __ldg(&ph[F_DIM + f]);
        float p2 = __ldg(&ph[2 * F_DIM + f]);
        const float* eqs = eq + (size_t)s * F3 + f * 3;
        float eq0 = eqs[0], eq1 = eqs[1], eq2 = eqs[2];

        float r[N_RBF] = {a0.x, a0.y, a0.z, a0.w,
                          a1.x, a1.y, a1.z, a1.w,
                          a2.x, a2.y, a2.z, a2.w,
                          a3.x, a3.y, a3.z, a3.w,
                          a4.x, a4.y, a4.z, a4.w};
        float W0 = br0, W1 = br1, W2 = br2;
#pragma unroll
        for (int k = 0; k < N_RBF; k++) {
            W0 = fmaf(r[k], wr0[k], W0);
            W1 = fmaf(r[k], wr1[k], W1);
            W2 = fmaf(r[k], wr2[k], W2);
        }
        float s1v = p1 * W1;
        float s2v = p2 * W2;
        acc0 = fmaf(p0, W0, acc0);
        aq0 = fmaf(eq0, s1v, fmaf(s2v, rd.x, aq0));
        aq1 = fmaf(eq1, s1v, fmaf(s2v, rd.y, aq1));
        aq2 = fmaf(eq2, s1v, fmaf(s2v, rd.z, aq2));
    }

    // epilogue: out = input + delta (written exactly once, no atomics)
    out_emb[node * F_DIM + f] = emb_table[zi * F_DIM + f] + acc0;
    float*       oe = out_eq + (size_t)node * F3 + f * 3;
    const float* ei = eq     + (size_t)node * F3 + f * 3;
    oe[0] = ei[0] + aq0;
    oe[1] = ei[1] + aq1;
    oe[2] = ei[2] + aq2;
}

// ---------------------------------------------------------
extern "C" void kernel_launch(void* const* d_in, const int* in_sizes, int n_in,
                              void* d_out, int out_size) {
    const float* pos       = (const float*)d_in[0];
    const float* eq        = (const float*)d_in[1];
    const float* emb_table = (const float*)d_in[2];
    const float* w_phi1    = (const float*)d_in[3];
    const float* b_phi1    = (const float*)d_in[4];
    const float* w_phi2    = (const float*)d_in[5];
    const float* b_phi2    = (const float*)d_in[6];
    const float* w_rbf     = (const float*)d_in[7];
    const float* b_rbf     = (const float*)d_in[8];
    const int*   z         = (const int*)d_in[9];
    const int*   edge_src  = (const int*)d_in[10];
    const int*   edge_dst  = (const int*)d_in[11];

    float* out     = (float*)d_out;
    float* out_emb = out;                                  // [N, 128]
    float* out_eq  = out + (size_t)N_NODES * F_DIM;        // [N, 128, 3]

    init_kernel<<<ZERO_NB + N_TYPES, 128>>>(emb_table, w_phi1, b_phi1, w_phi2, b_phi2);
    hist_kernel<<<(N_EDGES + 255) / 256, 256>>>(edge_dst);
    scan1_kernel<<<SCAN_NB, SCAN_B>>>();
    scan23_kernel<<<SCAN_NB, SCAN_B>>>();
    scatter_kernel<<<(N_EDGES + 255) / 256, 256>>>(edge_dst);
    geom_kernel<<<(N_EDGES + 255) / 256, 256>>>(pos, z, edge_src, edge_dst);
    main_kernel<<<N_NODES, 128>>>(eq, emb_table, w_rbf, b_rbf, z,
                                  out_emb, out_eq);
}

// round 7
// speedup vs baseline: 1.1735x; 1.1735x over previous
#include <cuda_runtime.h>
#include <math.h>

#define N_NODES 50000
#define N_EDGES 400000
#define F_DIM   128
#define N_TYPES 100
#define N_RBF   20
#define CUTOFF  5.0f
#define F3      (3 * F_DIM)   // 384

#define SCAN_B  256
#define SCAN_NB ((N_NODES + SCAN_B - 1) / SCAN_B)   // 196
#define HIST_NB ((N_EDGES + 255) / 256)             // 1563
#define PHI_NB  (N_TYPES / 2)                       // 50 (2 types per 256-thr block)

typedef unsigned long long ull;

// -------- device scratch (no allocations allowed; zero-initialized at load) --------
__device__ int   g_count[N_NODES];
__device__ int   g_start[N_NODES + 1];
__device__ int   g_cursor[N_NODES];
__device__ ull   g_scan_state[SCAN_NB];   // packed: (value<<2)|status; 1=agg,2=inclusive
__device__ float g_phi[N_TYPES * F3];     // 100 x 384

// per-edge packed row (dst-sorted order): [0..19]=rbf, [20..22]=rel*dist,
// [23]=pad, [24]=src bits, [25]=typ bits, [26..31]=pad  => 128 bytes
struct __align__(16) EdgeRow { float v[32]; };
__device__ EdgeRow g_edat[N_EDGES];       // 51.2 MB

// ---------------------------------------------------------
// Launch 0 (pre): hist blocks count edge_dst (g_count zeroed by previous
// call's cleanup / static init); phi blocks compute the 100-row MLP table.
__global__ void pre_kernel(const int* __restrict__ edge_dst,
                           const float* __restrict__ emb_table,
                           const float* __restrict__ w1, const float* __restrict__ b1,
                           const float* __restrict__ w2, const float* __restrict__ b2) {
    if (blockIdx.x < HIST_NB) {
        int e = blockIdx.x * 256 + threadIdx.x;
        if (e < N_EDGES) atomicAdd(&g_count[edge_dst[e]], 1);
        return;
    }
    // phi: 2 atom types per block (each 128-thread half does one type)
    int bb = blockIdx.x - HIST_NB;          // 0..49
    int half = threadIdx.x >> 7;            // 0/1
    int t = bb * 2 + half;                  // atom type
    int f = threadIdx.x & 127;
    __shared__ float es[2][F_DIM];
    __shared__ float hs[2][F_DIM];
    es[half][f] = emb_table[t * F_DIM + f];
    __syncthreads();
    float h = b1[f];
#pragma unroll 8
    for (int k = 0; k < F_DIM; k++)
        h = fmaf(es[half][k], w1[k * F_DIM + f], h);
    h = h / (1.0f + expf(-h));   // silu
    hs[half][f] = h;
    __syncthreads();
    float o0 = b2[f], o1 = b2[F_DIM + f], o2 = b2[2 * F_DIM + f];
#pragma unroll 8
    for (int k = 0; k < F_DIM; k++) {
        float hk = hs[half][k];
        const float* w2r = w2 + k * F3;
        o0 = fmaf(hk, w2r[f],             o0);
        o1 = fmaf(hk, w2r[F_DIM + f],     o1);
        o2 = fmaf(hk, w2r[2 * F_DIM + f], o2);
    }
    g_phi[t * F3 + f]             = o0;
    g_phi[t * F3 + F_DIM + f]     = o1;
    g_phi[t * F3 + 2 * F_DIM + f] = o2;
}

// ---------------------------------------------------------
// Launch 1: single-kernel decoupled-lookback exclusive scan of g_count
// -> g_start, g_cursor. g_scan_state zeroed by previous cleanup.
__global__ void scan_kernel() {
    __shared__ int wsum[SCAN_B / 32];
    __shared__ int s_prefix;
    int t = threadIdx.x;
    int b = blockIdx.x;
    int i = b * SCAN_B + t;
    int v = (i < N_NODES) ? g_count[i] : 0;

    // block-local inclusive scan
    int sv = v;
    for (int off = 1; off < 32; off <<= 1) {
        int u = __shfl_up_sync(0xffffffffu, sv, off);
        if ((t & 31) >= off) sv += u;
    }
    if ((t & 31) == 31) wsum[t >> 5] = sv;
    __syncthreads();
    if (t < SCAN_B / 32) {
        int s = wsum[t];
        for (int off = 1; off < SCAN_B / 32; off <<= 1) {
            int u = __shfl_up_sync(0xffu, s, off);
            if (t >= off) s += u;
        }
        wsum[t] = s;
    }
    __syncthreads();
    int warp = t >> 5;
    int incl = sv + ((warp > 0) ? wsum[warp - 1] : 0);
    int total = wsum[SCAN_B / 32 - 1];

    // decoupled lookback (thread 0)
    if (t == 0) {
        if (b == 0) {
            atomicExch(&g_scan_state[0], ((ull)total << 2) | 2ULL);
            s_prefix = 0;
            g_start[N_NODES] = N_EDGES;
        } else {
            atomicExch(&g_scan_state[b], ((ull)total << 2) | 1ULL);
            int prefix = 0;
            int j = b - 1;
            while (j >= 0) {
                ull st;
                do { st = atomicAdd(&g_scan_state[j], 0ULL); } while ((st & 3ULL) == 0ULL);
                prefix += (int)(st >> 2);
                if ((st & 3ULL) == 2ULL) break;
                j--;
            }
            atomicExch(&g_scan_state[b], ((ull)(prefix + total) << 2) | 2ULL);
            s_prefix = prefix;
        }
    }
    __syncthreads();
    int excl = s_prefix + incl - v;
    if (i < N_NODES) {
        g_start[i]  = excl;
        g_cursor[i] = excl;
    }
}

// ---------------------------------------------------------
// Launch 2: fused scatter + geometry. Each thread claims its dst-sorted slot
// and writes the complete 128-byte edge row there.
__global__ void sg_kernel(const float* __restrict__ pos,
                          const int*   __restrict__ z,
                          const int*   __restrict__ edge_src,
                          const int*   __restrict__ edge_dst) {
    int e = blockIdx.x * blockDim.x + threadIdx.x;
    if (e >= N_EDGES) return;
    int s = __ldg(&edge_src[e]);
    int d = __ldg(&edge_dst[e]);
    int p = atomicAdd(&g_cursor[d], 1);
    int ty = __ldg(&z[s]);
    float rx = __ldg(&pos[d * 3 + 0]) - __ldg(&pos[s * 3 + 0]);
    float ry = __ldg(&pos[d * 3 + 1]) - __ldg(&pos[s * 3 + 1]);
    float rz = __ldg(&pos[d * 3 + 2]) - __ldg(&pos[s * 3 + 2]);
    float dist = sqrtf(rx * rx + ry * ry + rz * rz);
    float inv  = 1.0f / dist;

    float row[32];
    float a = 3.14159265358979323846f * dist * (1.0f / CUTOFF);
    float s1, c1;
    sincosf(a, &s1, &c1);
    float twoc = 2.0f * c1;
    float sp = 0.0f, sc = s1;          // sin(0), sin(a)
#pragma unroll
    for (int k = 0; k < N_RBF; k++) {  // sin((k+1)a), stable Chebyshev recurrence
        row[k] = sc * inv;
        float nx = twoc * sc - sp;
        sp = sc; sc = nx;
    }
    row[20] = rx * dist;
    row[21] = ry * dist;
    row[22] = rz * dist;
    row[23] = 0.0f;
    row[24] = __int_as_float(s);
    row[25] = __int_as_float(ty);
    row[26] = row[27] = row[28] = row[29] = row[30] = row[31] = 0.0f;

    float4* dst4 = reinterpret_cast<float4*>(g_edat[p].v);
    const float4* src4 = reinterpret_cast<const float4*>(row);
#pragma unroll
    for (int j = 0; j < 8; j++) dst4[j] = src4[j];
}

// ---------------------------------------------------------
// Launch 3 (PROFILED): main. One block (128 threads) per destination node.
// Phase 1: thread f bulk-loads edge row f (7x LDG.128, fully parallel) into smem.
// Phase 2: identical to the proven 395.8us accumulate loop.
__global__ __launch_bounds__(128, 4)
void main_kernel(const float* __restrict__ eq,
                 const float* __restrict__ emb_table,
                 const float* __restrict__ w_rbf,
                 const float* __restrict__ b_rbf,
                 const int*   __restrict__ z,
                 float* __restrict__ out_emb,
                 float* __restrict__ out_eq) {
    int f = threadIdx.x;
    int node = blockIdx.x;

    int e0 = g_start[node];
    int e1 = __ldg(&g_start[node + 1]);
    int zi = __ldg(&z[node]);

    // per-thread w_rbf columns in registers (60 regs)
    float wr0[N_RBF], wr1[N_RBF], wr2[N_RBF];
#pragma unroll
    for (int k = 0; k < N_RBF; k++) {
        const float* row = w_rbf + k * F3;
        wr0[k] = row[f];
        wr1[k] = row[F_DIM + f];
        wr2[k] = row[2 * F_DIM + f];
    }
    const float br0 = b_rbf[f], br1 = b_rbf[F_DIM + f], br2 = b_rbf[2 * F_DIM + f];

    __shared__ __align__(16) float sh_rbf[128][N_RBF];   // 80B rows, 16B-aligned
    __shared__ float sh_rd[128][3];
    __shared__ int   sh_src[128];
    __shared__ int   sh_typ[128];

    int cnt = e1 - e0;
    float acc0 = 0.f, aq0 = 0.f, aq1 = 0.f, aq2 = 0.f;

    for (int base = 0; base < cnt; base += 128) {
        int nch = min(128, cnt - base);
        // phase 1: bulk-load pre-staged rows (independent 128B loads)
        if (f < nch) {
            const float4* row = reinterpret_cast<const float4*>(g_edat[e0 + base + f].v);
            float4 a0 = __ldg(row + 0);
            float4 a1 = __ldg(row + 1);
            float4 a2 = __ldg(row + 2);
            float4 a3 = __ldg(row + 3);
            float4 a4 = __ldg(row + 4);
            float4 rd = __ldg(row + 5);
            float4 mt = __ldg(row + 6);
            float4* rb4 = reinterpret_cast<float4*>(sh_rbf[f]);
            rb4[0] = a0; rb4[1] = a1; rb4[2] = a2; rb4[3] = a3; rb4[4] = a4;
            sh_rd[f][0] = rd.x;
            sh_rd[f][1] = rd.y;
            sh_rd[f][2] = rd.z;
            sh_src[f] = __float_as_int(mt.x);
            sh_typ[f] = __float_as_int(mt.y);
        }
        __syncthreads();
        // phase 2: all 128 threads accumulate over the chunk's edges
#pragma unroll 4
        for (int e = 0; e < nch; e++) {
            const float* ph = g_phi + sh_typ[e] * F3;
            int s = sh_src[e];
            const float* eqs = eq + (size_t)s * F3 + f * 3;
            float p0 = ph[f];
            float p1 = ph[F_DIM + f];
            float p2 = ph[2 * F_DIM + f];
            float eq0 = eqs[0], eq1 = eqs[1], eq2 = eqs[2];
            float W0 = br0, W1 = br1, W2 = br2;
#pragma unroll
            for (int k = 0; k < N_RBF; k++) {
                float r = sh_rbf[e][k];    // broadcast
                W0 = fmaf(r, wr0[k], W0);
                W1 = fmaf(r, wr1[k], W1);
                W2 = fmaf(r, wr2[k], W2);
            }
            float s1v = p1 * W1;
            float s2v = p2 * W2;
            acc0 = fmaf(p0, W0, acc0);
            aq0 = fmaf(eq0, s1v, fmaf(s2v, sh_rd[e][0], aq0));
            aq1 = fmaf(eq1, s1v, fmaf(s2v, sh_rd[e][1], aq1));
            aq2 = fmaf(eq2, s1v, fmaf(s2v, sh_rd[e][2], aq2));
        }
        __syncthreads();
    }

    // epilogue: out = input + delta (written exactly once, no atomics)
    out_emb[node * F_DIM + f] = emb_table[zi * F_DIM + f] + acc0;
    float*       oe = out_eq + (size_t)node * F3 + f * 3;
    const float* ei = eq     + (size_t)node * F3 + f * 3;
    oe[0] = ei[0] + aq0;
    oe[1] = ei[1] + aq1;
    oe[2] = ei[2] + aq2;
}

// ---------------------------------------------------------
// Launch 4: cleanup — reset histogram + scan state for the NEXT call.
// Runs every call (deterministic); module load provides the first zeroing.
__global__ void cleanup_kernel() {
    int i = blockIdx.x * blockDim.x + threadIdx.x;
    if (i < N_NODES) g_count[i] = 0;
    if (i < SCAN_NB) g_scan_state[i] = 0ULL;
}

// ---------------------------------------------------------
extern "C" void kernel_launch(void* const* d_in, const int* in_sizes, int n_in,
                              void* d_out, int out_size) {
    const float* pos       = (const float*)d_in[0];
    const float* eq        = (const float*)d_in[1];
    const float* emb_table = (const float*)d_in[2];
    const float* w_phi1    = (const float*)d_in[3];
    const float* b_phi1    = (const float*)d_in[4];
    const float* w_phi2    = (const float*)d_in[5];
    const float* b_phi2    = (const float*)d_in[6];
    const float* w_rbf     = (const float*)d_in[7];
    const float* b_rbf     = (const float*)d_in[8];
    const int*   z         = (const int*)d_in[9];
    const int*   edge_src  = (const int*)d_in[10];
    const int*   edge_dst  = (const int*)d_in[11];

    float* out     = (float*)d_out;
    float* out_emb = out;                                  // [N, 128]
    float* out_eq  = out + (size_t)N_NODES * F_DIM;        // [N, 128, 3]

    pre_kernel<<<HIST_NB + PHI_NB, 256>>>(edge_dst, emb_table, w_phi1, b_phi1,
                                          w_phi2, b_phi2);
    scan_kernel<<<SCAN_NB, SCAN_B>>>();
    sg_kernel<<<HIST_NB, 256>>>(pos, z, edge_src, edge_dst);
    main_kernel<<<N_NODES, 128>>>(eq, emb_table, w_rbf, b_rbf, z,
                                  out_emb, out_eq);
    cleanup_kernel<<<(N_NODES + 255) / 256, 256>>>();
}